// round 14
// baseline (speedup 1.0000x reference)
#include <cuda_runtime.h>
#include <math.h>
#include <stdint.h>

// ---------------- problem constants ----------------
#define IWm1   703            // IW-1
#define IHm1   255            // IH-1
#define FHh    32
#define FWw    88
#define NPIX   (FHh*FWw)      // 2816 pixels per image
#define NB     2              // batch (B*N)
#define NGP    (NB*NPIX)      // 5632
#define CIN    256
#define HID    64
#define DN     118            // depth bins
#define COUT   80
#define NOUT   198            // DN + COUT
#define NRr    128
#define NTH    256
#define NBIN   (NRr*NTH)      // 32768
#define DSTR   120            // padded depth-logit row stride
#define BN_EPS 1e-5f
#define HASHN  512            // hash entries == slots (worst case used here ~90)
#define WSTR   9              // s_W slot stride (9: conflict-free smem atomics)

// ---------------- device scratch (static, allocation-free) ----------------
// g_scratch is zeroed by k1 (spread across its blocks) before k3 runs.
// g_dlog padding columns [118..119] are never written; static zero-init keeps
// them 0.0 forever (softmax masks them anyway).
__device__ __align__(16) float g_h1[HID * NGP];             // hidden  [c][gp]
__device__ __align__(16) float g_dlog[NGP * DSTR];          // depth logits [gp][120]
__device__ __align__(16) float g_feat[NGP * COUT];          // features [gp][80]
__device__ __align__(16) float g_scratch[NB * NBIN * COUT]; // bev accum [b][bin][c]
__device__ float g_rad[NRr + 1];
__device__ float g_ang[NTH + 1];

// ---------------- K1: conv1 + BN1 + ReLU + scratch-zero + edge tables -----
// grid (11, 8), block 256, TWO pixels per thread.  h1 stored [o][gp].
__global__ void k1_conv1(const float* __restrict__ x,  const float* __restrict__ w1,
                         const float* __restrict__ b1, const float* __restrict__ g1,
                         const float* __restrict__ be1,const float* __restrict__ m1,
                         const float* __restrict__ v1) {
    __shared__ float4 ws4[CIN * 2];                  // [c][8] as 2x float4
    float* ws = (float*)ws4;
    int og = blockIdx.y;
    for (int i = threadIdx.x; i < 8 * CIN; i += 256) {
        int c = i >> 3, o = i & 7;
        ws[c * 8 + o] = w1[(og * 8 + o) * CIN + c];
    }

    // block (0,0): build edge tables ONCE (numpy float64 -> f32)
    if (blockIdx.x == 0 && blockIdx.y == 0) {
        int i = threadIdx.x;
        if (i <= NRr) {
            double t = (double)i / 128.0;
            g_rad[i] = (float)(1.0 + pow(t, 1.5) * 59.0);
        }
        if (i < NTH) g_ang[i] = (float)(-M_PI * 0.5 + (double)i * (M_PI / 256.0));
        if (i == 0)  g_ang[NTH] = (float)(M_PI * 0.5);   // index 256 (>255)
    }

    // zero my chunk of g_scratch (fire-and-forget stores, hidden under GEMM)
    {
        const int NBLK = 11 * 8;
        const size_t TOT4 = (size_t)NB * NBIN * COUT / 4;       // 1,310,720
        const size_t CH = (TOT4 + NBLK - 1) / NBLK;
        int bid = blockIdx.y * 11 + blockIdx.x;
        size_t lo = CH * bid + threadIdx.x, hi = CH * (bid + 1);
        if (hi > TOT4) hi = TOT4;
        float4* s4 = (float4*)g_scratch;
        for (size_t i = lo; i < hi; i += 256) s4[i] = make_float4(0, 0, 0, 0);
    }
    __syncthreads();

    int tid = threadIdx.x;
    int gpA = blockIdx.x * 512 + tid;                // 0..5631
    int gpB = gpA + 256;
    int bA = gpA / NPIX, pA = gpA - bA * NPIX;
    int bB = gpB / NPIX, pB = gpB - bB * NPIX;
    const float* xbA = x + (size_t)bA * CIN * NPIX + pA;
    const float* xbB = x + (size_t)bB * CIN * NPIX + pB;

    float acc0[8], acc1[8];
#pragma unroll
    for (int j = 0; j < 8; j++) { acc0[j] = 0.f; acc1[j] = 0.f; }

#pragma unroll 4
    for (int c = 0; c < CIN; c++) {
        float xv0 = xbA[(size_t)c * NPIX];
        float xv1 = xbB[(size_t)c * NPIX];
        float4 wa = ws4[c * 2], wb = ws4[c * 2 + 1];
        acc0[0] += xv0 * wa.x; acc0[1] += xv0 * wa.y;
        acc0[2] += xv0 * wa.z; acc0[3] += xv0 * wa.w;
        acc0[4] += xv0 * wb.x; acc0[5] += xv0 * wb.y;
        acc0[6] += xv0 * wb.z; acc0[7] += xv0 * wb.w;
        acc1[0] += xv1 * wa.x; acc1[1] += xv1 * wa.y;
        acc1[2] += xv1 * wa.z; acc1[3] += xv1 * wa.w;
        acc1[4] += xv1 * wb.x; acc1[5] += xv1 * wb.y;
        acc1[6] += xv1 * wb.z; acc1[7] += xv1 * wb.w;
    }
#pragma unroll
    for (int j = 0; j < 8; j++) {
        int o = og * 8 + j;
        float inv = __ldg(&g1[o]) / sqrtf(__ldg(&v1[o]) + BN_EPS);
        float sh  = __ldg(&be1[o]) - __ldg(&m1[o]) * inv;
        float bb  = __ldg(&b1[o]);
        g_h1[(size_t)o * NGP + gpA] = fmaxf((acc0[j] + bb) * inv + sh, 0.0f);
        g_h1[(size_t)o * NGP + gpB] = fmaxf((acc1[j] + bb) * inv + sh, 0.0f);
    }
}

// ---------------- K2a: conv2 (64->198) + BN2, 16 out x 2 px per thread ----
// grid (11, 13), block 256.  Stores staged through smem for coalescing.
__global__ void k2a_conv2(const float* __restrict__ w2, const float* __restrict__ b2,
                          const float* __restrict__ g2, const float* __restrict__ be2,
                          const float* __restrict__ m2, const float* __restrict__ v2) {
    __shared__ float4 ws4[HID * 4];                   // [c][16] as 4x float4
    __shared__ float  tile[256 * 17];                 // staging, pad 16->17
    float* ws = (float*)ws4;
    int og = blockIdx.y;                              // 0..12
    for (int i = threadIdx.x; i < 16 * HID; i += 256) {
        int c = i >> 4, o = i & 15;
        int oo = og * 16 + o;
        ws[c * 16 + o] = (oo < NOUT) ? w2[oo * HID + c] : 0.0f;
    }
    __syncthreads();

    int tid = threadIdx.x;
    int gpA = blockIdx.x * 512 + tid;
    int gpB = gpA + 256;

    float a0[16], a1[16];
#pragma unroll
    for (int j = 0; j < 16; j++) { a0[j] = 0.f; a1[j] = 0.f; }

#pragma unroll 4
    for (int c = 0; c < HID; c++) {
        float hv0 = g_h1[(size_t)c * NGP + gpA];
        float hv1 = g_h1[(size_t)c * NGP + gpB];
#pragma unroll
        for (int q = 0; q < 4; q++) {
            float4 w = ws4[c * 4 + q];
            a0[q * 4 + 0] += hv0 * w.x; a0[q * 4 + 1] += hv0 * w.y;
            a0[q * 4 + 2] += hv0 * w.z; a0[q * 4 + 3] += hv0 * w.w;
            a1[q * 4 + 0] += hv1 * w.x; a1[q * 4 + 1] += hv1 * w.y;
            a1[q * 4 + 2] += hv1 * w.z; a1[q * 4 + 3] += hv1 * w.w;
        }
    }
    // BN in registers
#pragma unroll
    for (int j = 0; j < 16; j++) {
        int o = og * 16 + j;
        if (o >= NOUT) continue;
        float inv = __ldg(&g2[o]) / sqrtf(__ldg(&v2[o]) + BN_EPS);
        float sh  = __ldg(&be2[o]) - __ldg(&m2[o]) * inv;
        float bb  = __ldg(&b2[o]);
        a0[j] = (a0[j] + bb) * inv + sh;
        a1[j] = (a1[j] + bb) * inv + sh;
    }

    int gpb = blockIdx.x * 512;
    // ---- pixel set 0: stage + coalesced store ----
#pragma unroll
    for (int j = 0; j < 16; j++) tile[tid * 17 + j] = a0[j];
    __syncthreads();
#pragma unroll
    for (int it = 0; it < 16; it++) {
        int i = it * 256 + tid;
        int p = i >> 4, j = i & 15;
        int o = og * 16 + j;
        float val = tile[p * 17 + j];
        int gp = gpb + p;
        if (o < DN)        g_dlog[(size_t)gp * DSTR + o] = val;
        else if (o < NOUT) g_feat[(size_t)gp * COUT + (o - DN)] = val;
    }
    __syncthreads();
    // ---- pixel set 1 ----
#pragma unroll
    for (int j = 0; j < 16; j++) tile[tid * 17 + j] = a1[j];
    __syncthreads();
#pragma unroll
    for (int it = 0; it < 16; it++) {
        int i = it * 256 + tid;
        int p = i >> 4, j = i & 15;
        int o = og * 16 + j;
        float val = tile[p * 17 + j];
        int gp = gpb + 256 + p;
        if (o < DN)        g_dlog[(size_t)gp * DSTR + o] = val;
        else if (o < NOUT) g_feat[(size_t)gp * COUT + (o - DN)] = val;
    }
}

// ---------------- reductions ----------------------------------------------
__device__ __forceinline__ void red_add_f4(float* addr, float a, float b, float c, float d) {
    asm volatile("red.global.add.v4.f32 [%0], {%1, %2, %3, %4};"
                 :: "l"(addr), "f"(a), "f"(b), "f"(c), "f"(d) : "memory");
}
__device__ __forceinline__ void red_add_f1(float* addr, float a) {
    asm volatile("red.global.add.f32 [%0], %1;" :: "l"(addr), "f"(a) : "memory");
}

// ---------------- hash insert: bin -> entry index (slot) ------------------
// CAS winners append their entry to the compact slot list (s_list/s_ns) so
// the flush only walks real slots.
__device__ __forceinline__ int hinsert(int bin, int* hkey, int* list, int* ns) {
    unsigned e = ((unsigned)bin * 2654435761u) >> 23;   // 9-bit home (0..511)
#pragma unroll 1
    for (int probe = 0; probe < HASHN; probe++) {
        int k = hkey[e];
        if (k == bin) return (int)e;
        if (k == -1) {
            int old = atomicCAS(&hkey[e], -1, bin);
            if (old == -1) {
                int idx = atomicAdd(ns, 1);
                list[idx] = (int)e;
                return (int)e;
            }
            if (old == bin) return (int)e;
        }
        e = (e + 1) & (HASHN - 1);
    }
    return -1;
}

// ---------------- K3: softmax + geometry + block-merged scatter -----------
// block = 8 warps = 8 pixels of ONE image column (same w, consecutive h).
// lane handles CONSECUTIVE depths d = 4*lane + k -> float4 logit load +
// register run-merge before the shared hash/atomic.
// grid = NB * FWw * (FHh/8) = 704, block 256.
__global__ __launch_bounds__(256) void k3_scatter(const float* __restrict__ rots,
                                                  const float* __restrict__ trans,
                                                  const float* __restrict__ intr) {
    __shared__ float  s_rad[NRr + 1];
    __shared__ float  s_ang[NTH + 1];
    __shared__ float4 s_F4[8][20];          // per-pixel features, 20 float4 = 80 ch
    __shared__ int    s_hkey[HASHN];        // bin or -1
    __shared__ int    s_list[HASHN];        // compact list of used entries
    __shared__ float  s_W[HASHN * WSTR];    // [slot][pixel], stride 9 (bank-safe)
    __shared__ int    s_ns;

    int tid = threadIdx.x;
    int warp = tid >> 5, lane = tid & 31;

    // decode block -> (b, column w, h-octet)
    int bi = blockIdx.x;
    int b  = bi / (FWw * (FHh / 8));
    int r_ = bi - b * (FWw * (FHh / 8));
    int h0 = (r_ / FWw) * 8;
    int wc = r_ - (r_ / FWw) * FWw;
    int hh = h0 + warp;
    int gp = b * NPIX + hh * FWw + wc;

    // ---- smem init (strided loops: indices 0..NRr / 0..NTH INCLUSIVE) ----
    if (tid == 0) s_ns = 0;
    for (int i = tid; i < HASHN; i += 256) s_hkey[i] = -1;
    for (int i = tid; i < HASHN * WSTR / 4; i += 256) ((float4*)s_W)[i] = make_float4(0, 0, 0, 0);
    for (int i = tid; i <= NRr; i += 256) s_rad[i] = g_rad[i];
    for (int i = tid; i <= NTH; i += 256) s_ang[i] = g_ang[i];   // covers s_ang[256]
    for (int i = tid; i < 8 * 20; i += 256) {
        int pw = i / 20, c4 = i - pw * 20;
        int gpp = b * NPIX + (h0 + pw) * FWw + wc;
        s_F4[pw][c4] = ((const float4*)(g_feat + (size_t)gpp * COUT))[c4];
    }
    __syncthreads();

    // ---- per-pixel constants ----
    float u  = (wc == FWw - 1) ? (float)IWm1 : (float)((double)wc * ((double)IWm1 / (FWw - 1)));
    float vv = (hh == FHh - 1) ? (float)IHm1 : (float)((double)hh * ((double)IHm1 / (FHh - 1)));

    const float* I = intr + b * 9;
    float fx = I[0], cx = I[2], fy = I[4], cy = I[5];
    const float* R = rots + b * 9;
    float r00 = R[0], r01 = R[1], r02 = R[2];
    float r10 = R[3], r11 = R[4], r12 = R[5];
    float t0 = trans[b * 3 + 0], t1 = trans[b * 3 + 1];
    float au = u - cx, av = vv - cy;

    // ---- softmax over 118 depth logits (d = 4*lane + k) ----
    const float* row = g_dlog + (size_t)gp * DSTR;
    float4 lv = *(const float4*)(row + 4 * lane);     // LDG.128, padding = 0.0
    float v[4] = {lv.x, lv.y, lv.z, lv.w};
    float mx = -3.4e38f;
#pragma unroll
    for (int k = 0; k < 4; k++) {
        if (4 * lane + k >= DN) v[k] = -3.4e38f;      // mask padding
        mx = fmaxf(mx, v[k]);
    }
#pragma unroll
    for (int s = 16; s > 0; s >>= 1) mx = fmaxf(mx, __shfl_xor_sync(0xffffffffu, mx, s));
    float sum = 0.f;
#pragma unroll
    for (int k = 0; k < 4; k++) {
        v[k] = (4 * lane + k < DN) ? __expf(v[k] - mx) : 0.0f;   // MUFU exp
        sum += v[k];
    }
#pragma unroll
    for (int s = 16; s > 0; s >>= 1) sum += __shfl_xor_sync(0xffffffffu, sum, s);
    float rinv = 1.0f / sum;
#pragma unroll
    for (int k = 0; k < 4; k++) v[k] *= rinv;        // dep[d]

    // ---- geometry -> bin; register run-merge, then hash+smem atomic ------
    float rad0 = s_rad[0], radN = s_rad[NRr];
    float ang0 = s_ang[0], angN = s_ang[NTH];
    float* sc = g_scratch + (size_t)b * NBIN * COUT;

    int   pb = -1;                                    // previous bin (run head)
    float ds = 0.0f;                                  // run depth-weight sum
#pragma unroll
    for (int k = 0; k < 5; k++) {                     // 5th iter = final flush
        int bin = -1;
        float dep = 0.0f;
        if (k < 4) {
            int d = 4 * lane + k;
            if (d < DN) {
                dep = v[k];
                float dd = 1.0f + 0.5f * (float)d;
                float px = (au * dd) / fx;
                float py = (av * dd) / fy;
                float xl = r00 * px + r01 * py + r02 * dd + t0;
                float yl = r10 * px + r11 * py + r12 * dd + t1;
                float r  = sqrtf(xl * xl + yl * yl);
                float th = atan2f(yl, xl);

                int ri = -1;
                if (r >= rad0 && r < radN) {
                    // MUFU estimate of inverse radial law; fixup is authoritative
                    float ri_f = __powf((r - 1.0f) * (1.0f / 59.0f), 0.66666667f) * 128.0f;
                    ri = (int)ri_f;
                    ri = min(max(ri, 0), NRr - 1);
                    while (ri > 0       && r <  s_rad[ri])     ri--;
                    while (ri < NRr - 1 && r >= s_rad[ri + 1]) ri++;
                    if (r < s_rad[ri] || r >= s_rad[ri + 1]) ri = -1;
                }
                int ti = -1;
                if (th >= ang0 && th < angN) {
                    ti = (int)((th - ang0) * (float)(256.0 / M_PI));
                    ti = min(max(ti, 0), NTH - 1);
                    while (ti > 0       && th <  s_ang[ti])     ti--;
                    while (ti < NTH - 1 && th >= s_ang[ti + 1]) ti++;
                    if (th < s_ang[ti] || th >= s_ang[ti + 1]) ti = -1;
                }
                if (ri >= 0 && ti >= 0) bin = ri * NTH + ti;
            }
        }
        if (bin == pb) {
            ds += dep;
        } else {
            if (pb >= 0) {                            // commit finished run
                int slot = hinsert(pb, s_hkey, s_list, &s_ns);
                if (slot >= 0) {
                    atomicAdd(&s_W[slot * WSTR + warp], ds);
                } else {
                    const float* fw = (const float*)&s_F4[warp][0];
                    float* dst = sc + (size_t)pb * COUT;
                    for (int c = 0; c < COUT; c++) red_add_f1(dst + c, ds * fw[c]);
                }
            }
            pb = bin;
            ds = dep;
        }
    }
    __syncthreads();

    // ---- flush: walk COMPACT slot list; one red.v4 per (slot, 4-ch chunk)
    int m = s_ns;
    for (int j = warp; j < m; j += 8) {
        int e   = s_list[j];
        int bin = s_hkey[e];                          // broadcast LDS
        if (lane < 20) {
            float4 acc = make_float4(0, 0, 0, 0);
#pragma unroll
            for (int i = 0; i < 8; i++) {
                float wji = s_W[e * WSTR + i];        // broadcast
                float4 f  = s_F4[i][lane];
                acc.x += wji * f.x; acc.y += wji * f.y;
                acc.z += wji * f.z; acc.w += wji * f.w;
            }
            red_add_f4(sc + (size_t)bin * COUT + lane * 4, acc.x, acc.y, acc.z, acc.w);
        }
    }
}

// ---------------- K4: transpose [b][bin][c] -> [b][c][bin] ----------------
// grid (512, 2), block 256.  64 bins x 80 channels per block, STG.128 out.
// (measured best config: 9.9us, occ 77%)
__global__ void k4_transpose(float* __restrict__ out) {
    __shared__ float tile[64 * 81];                   // pad 80->81
    int bb   = blockIdx.y;
    int bin0 = blockIdx.x * 64;
    const float4* src = (const float4*)(g_scratch + ((size_t)bb * NBIN + bin0) * COUT);
    for (int i = threadIdx.x; i < 64 * 20; i += 256) {           // 1280 float4
        int bl = i / 20, c4 = i - bl * 20;
        float4 vv = src[i];
        float* t = &tile[bl * 81 + c4 * 4];
        t[0] = vv.x; t[1] = vv.y; t[2] = vv.z; t[3] = vv.w;
    }
    __syncthreads();
    float4* dst4 = (float4*)(out + (size_t)bb * COUT * NBIN + bin0);
    for (int i = threadIdx.x; i < COUT * 16; i += 256) {         // 1280 float4
        int c = i >> 4, b4 = i & 15;
        float4 vv;
        vv.x = tile[(b4 * 4 + 0) * 81 + c];
        vv.y = tile[(b4 * 4 + 1) * 81 + c];
        vv.z = tile[(b4 * 4 + 2) * 81 + c];
        vv.w = tile[(b4 * 4 + 3) * 81 + c];
        dst4[((size_t)c * NBIN) / 4 + b4] = vv;
    }
}

// ---------------- launch -------------------------------------------------
extern "C" void kernel_launch(void* const* d_in, const int* in_sizes, int n_in,
                              void* d_out, int out_size) {
    (void)in_sizes; (void)n_in; (void)out_size;
    const float* x     = (const float*)d_in[0];
    const float* rots  = (const float*)d_in[1];
    const float* trans = (const float*)d_in[2];
    const float* intr  = (const float*)d_in[3];
    const float* w1    = (const float*)d_in[4];
    const float* b1    = (const float*)d_in[5];
    const float* g1    = (const float*)d_in[6];
    const float* be1   = (const float*)d_in[7];
    const float* m1    = (const float*)d_in[8];
    const float* v1    = (const float*)d_in[9];
    const float* w2    = (const float*)d_in[10];
    const float* b2    = (const float*)d_in[11];
    const float* g2    = (const float*)d_in[12];
    const float* be2   = (const float*)d_in[13];
    const float* m2    = (const float*)d_in[14];
    const float* v2    = (const float*)d_in[15];
    float* out = (float*)d_out;

    k1_conv1<<<dim3(NGP / 512, 8), 256>>>(x, w1, b1, g1, be1, m1, v1);
    k2a_conv2<<<dim3(NGP / 512, 13), 256>>>(w2, b2, g2, be2, m2, v2);
    k3_scatter<<<NB * FWw * (FHh / 8), 256>>>(rots, trans, intr);
    k4_transpose<<<dim3(NBIN / 64, NB), 256>>>(out);
}

// round 15
// speedup vs baseline: 1.2342x; 1.2342x over previous
#include <cuda_runtime.h>
#include <math.h>
#include <stdint.h>

// ---------------- problem constants ----------------
#define IWm1   703            // IW-1
#define IHm1   255            // IH-1
#define FHh    32
#define FWw    88
#define NPIX   (FHh*FWw)      // 2816 pixels per image
#define NB     2              // batch (B*N)
#define NGP    (NB*NPIX)      // 5632
#define CIN    256
#define HID    64
#define DN     118            // depth bins
#define COUT   80
#define NOUT   198            // DN + COUT
#define NRr    128
#define NTH    256
#define NBIN   (NRr*NTH)      // 32768
#define DSTR   120            // padded depth-logit row stride
#define BN_EPS 1e-5f
#define HASHN  512            // hash entries == slots (worst case used here ~90)
#define WSTR   9              // s_W slot stride (9: conflict-free smem atomics)

// ---------------- device scratch (static, allocation-free) ----------------
// g_scratch is zeroed by k1 (spread across its blocks) before k3 runs.
// g_dlog padding columns [118..119] are never written; static zero-init keeps
// them 0.0 forever (softmax masks them anyway).
__device__ __align__(16) float g_h1[HID * NGP];             // hidden  [c][gp]
__device__ __align__(16) float g_dlog[NGP * DSTR];          // depth logits [gp][120]
__device__ __align__(16) float g_feat[NGP * COUT];          // features [gp][80]
__device__ __align__(16) float g_scratch[NB * NBIN * COUT]; // bev accum [b][bin][c]
__device__ float g_rad[NRr + 1];
__device__ float g_ang[NTH + 1];

// ---------------- K1: conv1 + BN1 + ReLU + scratch-zero + edge tables -----
// grid (22, 8), block 256 (>=148 blocks: keep every SM fed).  h1 [o][gp].
__global__ void k1_conv1(const float* __restrict__ x,  const float* __restrict__ w1,
                         const float* __restrict__ b1, const float* __restrict__ g1,
                         const float* __restrict__ be1,const float* __restrict__ m1,
                         const float* __restrict__ v1) {
    __shared__ float4 ws4[CIN * 2];                  // [c][8] as 2x float4
    float* ws = (float*)ws4;
    int og = blockIdx.y;
    for (int i = threadIdx.x; i < 8 * CIN; i += 256) {
        int c = i >> 3, o = i & 7;
        ws[c * 8 + o] = w1[(og * 8 + o) * CIN + c];
    }

    // block (0,0): build edge tables ONCE (numpy float64 -> f32)
    if (blockIdx.x == 0 && blockIdx.y == 0) {
        int i = threadIdx.x;
        if (i <= NRr) {
            double t = (double)i / 128.0;
            g_rad[i] = (float)(1.0 + pow(t, 1.5) * 59.0);
        }
        if (i < NTH) g_ang[i] = (float)(-M_PI * 0.5 + (double)i * (M_PI / 256.0));
        if (i == 0)  g_ang[NTH] = (float)(M_PI * 0.5);   // index 256 (>255)
    }

    // zero my chunk of g_scratch (fire-and-forget stores, hidden under GEMM)
    {
        const int NBLK = 22 * 8;
        const size_t TOT4 = (size_t)NB * NBIN * COUT / 4;       // 1,310,720
        const size_t CH = (TOT4 + NBLK - 1) / NBLK;
        int bid = blockIdx.y * 22 + blockIdx.x;
        size_t lo = CH * bid + threadIdx.x, hi = CH * (bid + 1);
        if (hi > TOT4) hi = TOT4;
        float4* s4 = (float4*)g_scratch;
        for (size_t i = lo; i < hi; i += 256) s4[i] = make_float4(0, 0, 0, 0);
    }
    __syncthreads();

    int gp = blockIdx.x * 256 + threadIdx.x;         // 0..5631
    int b  = gp / NPIX;
    int p  = gp - b * NPIX;
    const float* xb = x + (size_t)b * CIN * NPIX + p;

    float acc[8];
#pragma unroll
    for (int j = 0; j < 8; j++) acc[j] = 0.f;

#pragma unroll 8
    for (int c = 0; c < CIN; c++) {
        float xv = xb[(size_t)c * NPIX];
        float4 wa = ws4[c * 2], wb = ws4[c * 2 + 1];
        acc[0] += xv * wa.x; acc[1] += xv * wa.y;
        acc[2] += xv * wa.z; acc[3] += xv * wa.w;
        acc[4] += xv * wb.x; acc[5] += xv * wb.y;
        acc[6] += xv * wb.z; acc[7] += xv * wb.w;
    }
#pragma unroll
    for (int j = 0; j < 8; j++) {
        int o = og * 8 + j;
        float inv = __ldg(&g1[o]) / sqrtf(__ldg(&v1[o]) + BN_EPS);
        float val = (acc[j] + __ldg(&b1[o])) * inv + (__ldg(&be1[o]) - __ldg(&m1[o]) * inv);
        g_h1[(size_t)o * NGP + gp] = fmaxf(val, 0.0f);
    }
}

// ---------------- K2a: conv2 (64->198) + BN2, 16 outputs per block --------
// grid (22, 13), block 256 (286 blocks).  Stores staged through smem so a
// warp writes 2 pixels x 16 contiguous floats per instruction (was 32 lines).
__global__ void k2a_conv2(const float* __restrict__ w2, const float* __restrict__ b2,
                          const float* __restrict__ g2, const float* __restrict__ be2,
                          const float* __restrict__ m2, const float* __restrict__ v2) {
    __shared__ float4 ws4[HID * 4];                   // [c][16] as 4x float4
    __shared__ float  tile[256 * 17];                 // staging, pad 16->17
    float* ws = (float*)ws4;
    int og = blockIdx.y;                              // 0..12
    for (int i = threadIdx.x; i < 16 * HID; i += 256) {
        int c = i >> 4, o = i & 15;
        int oo = og * 16 + o;
        ws[c * 16 + o] = (oo < NOUT) ? w2[oo * HID + c] : 0.0f;
    }
    __syncthreads();

    int tid = threadIdx.x;
    int gp = blockIdx.x * 256 + tid;
    float acc[16];
#pragma unroll
    for (int j = 0; j < 16; j++) acc[j] = 0.f;

#pragma unroll 4
    for (int c = 0; c < HID; c++) {
        float hv = g_h1[(size_t)c * NGP + gp];
#pragma unroll
        for (int q = 0; q < 4; q++) {
            float4 w = ws4[c * 4 + q];
            acc[q * 4 + 0] += hv * w.x; acc[q * 4 + 1] += hv * w.y;
            acc[q * 4 + 2] += hv * w.z; acc[q * 4 + 3] += hv * w.w;
        }
    }
    // BN in registers, stage to smem (tid*17+j: stride-17 => conflict-free)
#pragma unroll
    for (int j = 0; j < 16; j++) {
        int o = og * 16 + j;
        float val = 0.0f;
        if (o < NOUT) {
            float inv = __ldg(&g2[o]) / sqrtf(__ldg(&v2[o]) + BN_EPS);
            float sh  = __ldg(&be2[o]) - __ldg(&m2[o]) * inv;
            val = (acc[j] + __ldg(&b2[o])) * inv + sh;
        }
        tile[tid * 17 + j] = val;
    }
    __syncthreads();

    // coalesced store: i -> (pixel p, output j); 16 contiguous floats/pixel
    int gpb = blockIdx.x * 256;
#pragma unroll
    for (int it = 0; it < 16; it++) {
        int i = it * 256 + tid;
        int p = i >> 4, j = i & 15;
        int o = og * 16 + j;
        float val = tile[p * 17 + j];
        int gpp = gpb + p;
        if (o < DN)        g_dlog[(size_t)gpp * DSTR + o] = val;
        else if (o < NOUT) g_feat[(size_t)gpp * COUT + (o - DN)] = val;
    }
}

// ---------------- reductions ----------------------------------------------
__device__ __forceinline__ void red_add_f4(float* addr, float a, float b, float c, float d) {
    asm volatile("red.global.add.v4.f32 [%0], {%1, %2, %3, %4};"
                 :: "l"(addr), "f"(a), "f"(b), "f"(c), "f"(d) : "memory");
}
__device__ __forceinline__ void red_add_f1(float* addr, float a) {
    asm volatile("red.global.add.f32 [%0], %1;" :: "l"(addr), "f"(a) : "memory");
}

// ---------------- hash insert: bin -> entry index (slot) ------------------
// CAS winners append their entry to the compact slot list (s_list/s_ns) so
// the flush only walks real slots.
__device__ __forceinline__ int hinsert(int bin, int* hkey, int* list, int* ns) {
    unsigned e = ((unsigned)bin * 2654435761u) >> 23;   // 9-bit home (0..511)
#pragma unroll 1
    for (int probe = 0; probe < HASHN; probe++) {
        int k = hkey[e];
        if (k == bin) return (int)e;
        if (k == -1) {
            int old = atomicCAS(&hkey[e], -1, bin);
            if (old == -1) {
                int idx = atomicAdd(ns, 1);
                list[idx] = (int)e;
                return (int)e;
            }
            if (old == bin) return (int)e;
        }
        e = (e + 1) & (HASHN - 1);
    }
    return -1;
}

// ---------------- K3: softmax + geometry + block-merged scatter -----------
// block = 8 warps = 8 pixels of ONE image column (same w, consecutive h).
// lane handles CONSECUTIVE depths d = 4*lane + k -> float4 logit load +
// register run-merge before the shared hash/atomic.
// grid = NB * FWw * (FHh/8) = 704, block 256.
__global__ __launch_bounds__(256) void k3_scatter(const float* __restrict__ rots,
                                                  const float* __restrict__ trans,
                                                  const float* __restrict__ intr) {
    __shared__ float  s_rad[NRr + 1];
    __shared__ float  s_ang[NTH + 1];
    __shared__ float4 s_F4[8][20];          // per-pixel features, 20 float4 = 80 ch
    __shared__ int    s_hkey[HASHN];        // bin or -1
    __shared__ int    s_list[HASHN];        // compact list of used entries
    __shared__ float  s_W[HASHN * WSTR];    // [slot][pixel], stride 9 (bank-safe)
    __shared__ int    s_ns;

    int tid = threadIdx.x;
    int warp = tid >> 5, lane = tid & 31;

    // decode block -> (b, column w, h-octet)
    int bi = blockIdx.x;
    int b  = bi / (FWw * (FHh / 8));
    int r_ = bi - b * (FWw * (FHh / 8));
    int h0 = (r_ / FWw) * 8;
    int wc = r_ - (r_ / FWw) * FWw;
    int hh = h0 + warp;
    int gp = b * NPIX + hh * FWw + wc;

    // ---- smem init (strided loops: indices 0..NRr / 0..NTH INCLUSIVE) ----
    if (tid == 0) s_ns = 0;
    for (int i = tid; i < HASHN; i += 256) s_hkey[i] = -1;
    for (int i = tid; i < HASHN * WSTR / 4; i += 256) ((float4*)s_W)[i] = make_float4(0, 0, 0, 0);
    for (int i = tid; i <= NRr; i += 256) s_rad[i] = g_rad[i];
    for (int i = tid; i <= NTH; i += 256) s_ang[i] = g_ang[i];   // covers s_ang[256]
    for (int i = tid; i < 8 * 20; i += 256) {
        int pw = i / 20, c4 = i - pw * 20;
        int gpp = b * NPIX + (h0 + pw) * FWw + wc;
        s_F4[pw][c4] = ((const float4*)(g_feat + (size_t)gpp * COUT))[c4];
    }
    __syncthreads();

    // ---- per-pixel constants ----
    float u  = (wc == FWw - 1) ? (float)IWm1 : (float)((double)wc * ((double)IWm1 / (FWw - 1)));
    float vv = (hh == FHh - 1) ? (float)IHm1 : (float)((double)hh * ((double)IHm1 / (FHh - 1)));

    const float* I = intr + b * 9;
    float fx = I[0], cx = I[2], fy = I[4], cy = I[5];
    const float* R = rots + b * 9;
    float r00 = R[0], r01 = R[1], r02 = R[2];
    float r10 = R[3], r11 = R[4], r12 = R[5];
    float t0 = trans[b * 3 + 0], t1 = trans[b * 3 + 1];
    float au = u - cx, av = vv - cy;

    // ---- softmax over 118 depth logits (d = 4*lane + k) ----
    const float* row = g_dlog + (size_t)gp * DSTR;
    float4 lv = *(const float4*)(row + 4 * lane);     // LDG.128, padding = 0.0
    float v[4] = {lv.x, lv.y, lv.z, lv.w};
    float mx = -3.4e38f;
#pragma unroll
    for (int k = 0; k < 4; k++) {
        if (4 * lane + k >= DN) v[k] = -3.4e38f;      // mask padding
        mx = fmaxf(mx, v[k]);
    }
#pragma unroll
    for (int s = 16; s > 0; s >>= 1) mx = fmaxf(mx, __shfl_xor_sync(0xffffffffu, mx, s));
    float sum = 0.f;
#pragma unroll
    for (int k = 0; k < 4; k++) {
        v[k] = (4 * lane + k < DN) ? __expf(v[k] - mx) : 0.0f;   // MUFU exp
        sum += v[k];
    }
#pragma unroll
    for (int s = 16; s > 0; s >>= 1) sum += __shfl_xor_sync(0xffffffffu, sum, s);
    float rinv = 1.0f / sum;
#pragma unroll
    for (int k = 0; k < 4; k++) v[k] *= rinv;        // dep[d]

    // ---- geometry -> bin; register run-merge, then hash+smem atomic ------
    float rad0 = s_rad[0], radN = s_rad[NRr];
    float ang0 = s_ang[0], angN = s_ang[NTH];
    float* sc = g_scratch + (size_t)b * NBIN * COUT;

    int   pb = -1;                                    // previous bin (run head)
    float ds = 0.0f;                                  // run depth-weight sum
#pragma unroll
    for (int k = 0; k < 5; k++) {                     // 5th iter = final flush
        int bin = -1;
        float dep = 0.0f;
        if (k < 4) {
            int d = 4 * lane + k;
            if (d < DN) {
                dep = v[k];
                float dd = 1.0f + 0.5f * (float)d;
                float px = (au * dd) / fx;
                float py = (av * dd) / fy;
                float xl = r00 * px + r01 * py + r02 * dd + t0;
                float yl = r10 * px + r11 * py + r12 * dd + t1;
                float r  = sqrtf(xl * xl + yl * yl);
                float th = atan2f(yl, xl);

                int ri = -1;
                if (r >= rad0 && r < radN) {
                    // MUFU estimate of inverse radial law; fixup is authoritative
                    float ri_f = __powf((r - 1.0f) * (1.0f / 59.0f), 0.66666667f) * 128.0f;
                    ri = (int)ri_f;
                    ri = min(max(ri, 0), NRr - 1);
                    while (ri > 0       && r <  s_rad[ri])     ri--;
                    while (ri < NRr - 1 && r >= s_rad[ri + 1]) ri++;
                    if (r < s_rad[ri] || r >= s_rad[ri + 1]) ri = -1;
                }
                int ti = -1;
                if (th >= ang0 && th < angN) {
                    ti = (int)((th - ang0) * (float)(256.0 / M_PI));
                    ti = min(max(ti, 0), NTH - 1);
                    while (ti > 0       && th <  s_ang[ti])     ti--;
                    while (ti < NTH - 1 && th >= s_ang[ti + 1]) ti++;
                    if (th < s_ang[ti] || th >= s_ang[ti + 1]) ti = -1;
                }
                if (ri >= 0 && ti >= 0) bin = ri * NTH + ti;
            }
        }
        if (bin == pb) {
            ds += dep;
        } else {
            if (pb >= 0) {                            // commit finished run
                int slot = hinsert(pb, s_hkey, s_list, &s_ns);
                if (slot >= 0) {
                    atomicAdd(&s_W[slot * WSTR + warp], ds);
                } else {
                    const float* fw = (const float*)&s_F4[warp][0];
                    float* dst = sc + (size_t)pb * COUT;
                    for (int c = 0; c < COUT; c++) red_add_f1(dst + c, ds * fw[c]);
                }
            }
            pb = bin;
            ds = dep;
        }
    }
    __syncthreads();

    // ---- flush: walk COMPACT slot list; one red.v4 per (slot, 4-ch chunk)
    int m = s_ns;
    for (int j = warp; j < m; j += 8) {
        int e   = s_list[j];
        int bin = s_hkey[e];                          // broadcast LDS
        if (lane < 20) {
            float4 acc = make_float4(0, 0, 0, 0);
#pragma unroll
            for (int i = 0; i < 8; i++) {
                float wji = s_W[e * WSTR + i];        // broadcast
                float4 f  = s_F4[i][lane];
                acc.x += wji * f.x; acc.y += wji * f.y;
                acc.z += wji * f.z; acc.w += wji * f.w;
            }
            red_add_f4(sc + (size_t)bin * COUT + lane * 4, acc.x, acc.y, acc.z, acc.w);
        }
    }
}

// ---------------- K4: transpose [b][bin][c] -> [b][c][bin] ----------------
// grid (512, 2), block 256.  64 bins x 80 channels per block, STG.128 out.
// (measured best config: 9.9us, occ 77%)
__global__ void k4_transpose(float* __restrict__ out) {
    __shared__ float tile[64 * 81];                   // pad 80->81
    int bb   = blockIdx.y;
    int bin0 = blockIdx.x * 64;
    const float4* src = (const float4*)(g_scratch + ((size_t)bb * NBIN + bin0) * COUT);
    for (int i = threadIdx.x; i < 64 * 20; i += 256) {           // 1280 float4
        int bl = i / 20, c4 = i - bl * 20;
        float4 vv = src[i];
        float* t = &tile[bl * 81 + c4 * 4];
        t[0] = vv.x; t[1] = vv.y; t[2] = vv.z; t[3] = vv.w;
    }
    __syncthreads();
    float4* dst4 = (float4*)(out + (size_t)bb * COUT * NBIN + bin0);
    for (int i = threadIdx.x; i < COUT * 16; i += 256) {         // 1280 float4
        int c = i >> 4, b4 = i & 15;
        float4 vv;
        vv.x = tile[(b4 * 4 + 0) * 81 + c];
        vv.y = tile[(b4 * 4 + 1) * 81 + c];
        vv.z = tile[(b4 * 4 + 2) * 81 + c];
        vv.w = tile[(b4 * 4 + 3) * 81 + c];
        dst4[((size_t)c * NBIN) / 4 + b4] = vv;
    }
}

// ---------------- launch -------------------------------------------------
extern "C" void kernel_launch(void* const* d_in, const int* in_sizes, int n_in,
                              void* d_out, int out_size) {
    (void)in_sizes; (void)n_in; (void)out_size;
    const float* x     = (const float*)d_in[0];
    const float* rots  = (const float*)d_in[1];
    const float* trans = (const float*)d_in[2];
    const float* intr  = (const float*)d_in[3];
    const float* w1    = (const float*)d_in[4];
    const float* b1    = (const float*)d_in[5];
    const float* g1    = (const float*)d_in[6];
    const float* be1   = (const float*)d_in[7];
    const float* m1    = (const float*)d_in[8];
    const float* v1    = (const float*)d_in[9];
    const float* w2    = (const float*)d_in[10];
    const float* b2    = (const float*)d_in[11];
    const float* g2    = (const float*)d_in[12];
    const float* be2   = (const float*)d_in[13];
    const float* m2    = (const float*)d_in[14];
    const float* v2    = (const float*)d_in[15];
    float* out = (float*)d_out;

    k1_conv1<<<dim3(NGP / 256, 8), 256>>>(x, w1, b1, g1, be1, m1, v1);
    k2a_conv2<<<dim3(NGP / 256, 13), 256>>>(w2, b2, g2, be2, m2, v2);
    k3_scatter<<<NB * FWw * (FHh / 8), 256>>>(rots, trans, intr);
    k4_transpose<<<dim3(NBIN / 64, NB), 256>>>(out);
}